// round 13
// baseline (speedup 1.0000x reference)
#include <cuda_runtime.h>
#include <cuda_fp16.h>
#include <math.h>
#include <stdint.h>

// ---------------------------------------------------------------------------
// Problem constants
// ---------------------------------------------------------------------------
#define CC      128
#define TN      64
#define NCOND   4
#define NVOX    32768
#define NTILES  512
#define NB      2
#define NGROUPS 8
#define NUNITS  (NB*NTILES)     // 1024 (b, tile) work units
#define NCTA    148             // persistent CTAs (one per SM)

// smem byte offsets. fp16 weight = 32KB; WoT fp32 = 64KB; Y2 att fp32 = 32KB.
#define OFF_WQ   0
#define OFF_WK   32768
#define OFF_WV   65536
#define OFF_WOT  98304      // Wo^T fp32 [k][co] rows of 512B (64KB)
#define OFF_Y0   163840     // activation buffer 0 [n=64][k=128] fp16 swizzled
#define OFF_Y1   180224     // activation buffer 1
#define OFF_Y2   196608     // attention output fp32 [co=128][vox=64] (32KB)
#define SMEM_REQ (229376 + 1024)

typedef unsigned long long ull;

// ---------------------------------------------------------------------------
// global scratch (no allocations allowed)
// ---------------------------------------------------------------------------
__device__ __half g_w[3][CC*CC];    // Wq,Wk,Wv fp16 — swizzled [co][k]
__device__ float  g_woT[CC*CC];     // Wo fp32 transposed [k][co]
__device__ float  g_sum[NB*NGROUPS*NTILES];
__device__ float  g_sq [NB*NGROUPS*NTILES];
__device__ float2 g_stats[NB*NGROUPS];

// ---------------------------------------------------------------------------
// PTX wrappers
// ---------------------------------------------------------------------------
__device__ __forceinline__ uint32_t smem_to_u32(const void* p) {
    uint32_t a;
    asm("{ .reg .u64 t; cvta.to.shared.u64 t, %1; cvt.u32.u64 %0, t; }" : "=r"(a) : "l"(p));
    return a;
}
__device__ __forceinline__ void ldsm4(uint32_t r[4], uint32_t addr) {
    asm volatile("ldmatrix.sync.aligned.m8n8.x4.shared.b16 {%0,%1,%2,%3}, [%4];"
                 : "=r"(r[0]), "=r"(r[1]), "=r"(r[2]), "=r"(r[3]) : "r"(addr));
}
__device__ __forceinline__ void mma16816(float d[4], const uint32_t a[4],
                                         uint32_t b0, uint32_t b1) {
    asm volatile("mma.sync.aligned.m16n8k16.row.col.f32.f16.f16.f32 "
                 "{%0,%1,%2,%3}, {%4,%5,%6,%7}, {%8,%9}, {%0,%1,%2,%3};"
                 : "+f"(d[0]), "+f"(d[1]), "+f"(d[2]), "+f"(d[3])
                 : "r"(a[0]), "r"(a[1]), "r"(a[2]), "r"(a[3]), "r"(b0), "r"(b1));
}

// packed f32x2 helpers (FFMA2 path — FMA pipe)
__device__ __forceinline__ ull dup2(float a) {
    ull r; asm("mov.b64 %0, {%1, %1};" : "=l"(r) : "f"(a)); return r;
}
__device__ __forceinline__ float2 unpack2(ull v) {
    float2 r; asm("mov.b64 {%0, %1}, %2;" : "=f"(r.x), "=f"(r.y) : "l"(v)); return r;
}
__device__ __forceinline__ void ffma2(ull& d, ull a, ull b) {
    asm("fma.rn.f32x2 %0, %1, %2, %0;" : "+l"(d) : "l"(a), "l"(b));
}

// swizzled byte offset inside a [rows][128] fp16 tile with 256B rows
__device__ __forceinline__ uint32_t swz(int row, int k) {
    return (uint32_t)(row * 256 + ((((k >> 3) ^ (row & 7)) & 15) << 4) + (k & 7) * 2);
}
__device__ __forceinline__ uint32_t pkhalf2(float lo, float hi) {
    __half2 h = __floats2half2_rn(lo, hi);
    uint32_t u;
    memcpy(&u, &h, 4);
    return u;
}

// ---------------------------------------------------------------------------
// fp16 MMA GEMMs
// ---------------------------------------------------------------------------
__device__ __forceinline__ void gemm1(float acc[8][4], uint32_t wa, uint32_t y,
                                      int w, int lane) {
    const int row  = lane & 15;
    const int half = lane >> 4;
#pragma unroll
    for (int kc = 0; kc < 8; kc++) {
        const uint32_t uoff = (uint32_t)((((2*kc + half) ^ (row & 7)) & 15) << 4);
        uint32_t A[4];
        ldsm4(A, wa + (uint32_t)(16*w + row)*256 + uoff);
#pragma unroll
        for (int nb2 = 0; nb2 < 4; nb2++) {
            uint32_t B[4];
            ldsm4(B, y + (uint32_t)(16*nb2 + row)*256 + uoff);
            mma16816(acc[2*nb2],   A, B[0], B[2]);
            mma16816(acc[2*nb2+1], A, B[1], B[3]);
        }
    }
}

__device__ __forceinline__ void gemm1_kv(float kf[8][4], float vf[8][4],
                                         uint32_t wk_, uint32_t wv_, uint32_t y,
                                         int w, int lane) {
    const int row  = lane & 15;
    const int half = lane >> 4;
#pragma unroll
    for (int kc = 0; kc < 8; kc++) {
        const uint32_t uoff = (uint32_t)((((2*kc + half) ^ (row & 7)) & 15) << 4);
        const uint32_t arow = (uint32_t)(16*w + row)*256 + uoff;
        uint32_t KA[4], VA[4];
        ldsm4(KA, wk_ + arow);
        ldsm4(VA, wv_ + arow);
#pragma unroll
        for (int nb2 = 0; nb2 < 4; nb2++) {
            uint32_t B[4];
            ldsm4(B, y + (uint32_t)(16*nb2 + row)*256 + uoff);
            mma16816(kf[2*nb2],   KA, B[0], B[2]);
            mma16816(kf[2*nb2+1], KA, B[1], B[3]);
            mma16816(vf[2*nb2],   VA, B[0], B[2]);
            mma16816(vf[2*nb2+1], VA, B[1], B[3]);
        }
    }
}

__device__ __forceinline__ void add_bias_frag(float acc[8][4], const float* __restrict__ bias,
                                              int w, int lane) {
    float b0 = __ldg(&bias[16*w + (lane >> 2)]);
    float b1 = __ldg(&bias[16*w + (lane >> 2) + 8]);
#pragma unroll
    for (int nb = 0; nb < 8; nb++) {
        acc[nb][0] += b0; acc[nb][1] += b0;
        acc[nb][2] += b1; acc[nb][3] += b1;
    }
}

// ---------------------------------------------------------------------------
// scalar O-GEMM chunk (FMA pipe, packed f32x2): k in [16s, 16s+16)
// acc2[p][j] = pairs (co0+2p, co0+2p+1) x vox (n0+j). WoT [k][co] fp32,
// Y2 att [k][vox] fp32 — both smem.
// ---------------------------------------------------------------------------
__device__ __forceinline__ void o_chunk(ull acc2[4][4], const char* smb, int s,
                                        int co0, int n0) {
    const float* wot = (const float*)(smb + OFF_WOT);
    const float* y2  = (const float*)(smb + OFF_Y2);
#pragma unroll
    for (int kk = 0; kk < 16; kk++) {
        int k = s*16 + kk;
        float4 y = *(const float4*)(y2 + k*TN + n0);
        ulonglong2 wA = *(const ulonglong2*)(wot + k*CC + co0);
        ulonglong2 wB = *(const ulonglong2*)(wot + k*CC + co0 + 4);
        ull y0 = dup2(y.x), y1 = dup2(y.y), y2v = dup2(y.z), y3 = dup2(y.w);
        ffma2(acc2[0][0], wA.x, y0); ffma2(acc2[0][1], wA.x, y1);
        ffma2(acc2[0][2], wA.x, y2v); ffma2(acc2[0][3], wA.x, y3);
        ffma2(acc2[1][0], wA.y, y0); ffma2(acc2[1][1], wA.y, y1);
        ffma2(acc2[1][2], wA.y, y2v); ffma2(acc2[1][3], wA.y, y3);
        ffma2(acc2[2][0], wB.x, y0); ffma2(acc2[2][1], wB.x, y1);
        ffma2(acc2[2][2], wB.x, y2v); ffma2(acc2[2][3], wB.x, y3);
        ffma2(acc2[3][0], wB.y, y0); ffma2(acc2[3][1], wB.y, y1);
        ffma2(acc2[3][2], wB.y, y2v); ffma2(acc2[3][3], wB.y, y3);
    }
}

// epilogue for the offloaded O: bias + residual + store + GN partials
__device__ __forceinline__ void o_epilogue(ull acc2[4][4],
                                           const float* __restrict__ dec,
                                           float* __restrict__ out,
                                           const float* __restrict__ bo,
                                           int pb, int ptile, int tid) {
    const int cy = tid >> 4, nx = tid & 15;
    const int co0 = cy*8, n0 = nx*4;
    const size_t voxBase = (size_t)ptile * TN;
    const float* decp = dec + (size_t)pb*CC*NVOX + voxBase;
    float* outp = out + (size_t)pb*CC*NVOX + voxBase;
    float s1 = 0.0f, s2 = 0.0f;
#pragma unroll
    for (int p = 0; p < 4; p++) {
        float bo0 = __ldg(&bo[co0 + 2*p]);
        float bo1 = __ldg(&bo[co0 + 2*p + 1]);
        float4 r0 = *(const float4*)(decp + (size_t)(co0+2*p)*NVOX + n0);
        float4 r1 = *(const float4*)(decp + (size_t)(co0+2*p+1)*NVOX + n0);
        float2 a0 = unpack2(acc2[p][0]);
        float2 a1 = unpack2(acc2[p][1]);
        float2 a2 = unpack2(acc2[p][2]);
        float2 a3 = unpack2(acc2[p][3]);
        float u0 = a0.x + bo0 + r0.x, u1 = a1.x + bo0 + r0.y;
        float u2 = a2.x + bo0 + r0.z, u3 = a3.x + bo0 + r0.w;
        float v0 = a0.y + bo1 + r1.x, v1 = a1.y + bo1 + r1.y;
        float v2 = a2.y + bo1 + r1.z, v3 = a3.y + bo1 + r1.w;
        *(float4*)(outp + (size_t)(co0+2*p)*NVOX + n0)   = make_float4(u0, u1, u2, u3);
        *(float4*)(outp + (size_t)(co0+2*p+1)*NVOX + n0) = make_float4(v0, v1, v2, v3);
        s1 += (u0 + u1) + (u2 + u3) + (v0 + v1) + (v2 + v3);
        s2 += fmaf(u0, u0, u1*u1) + fmaf(u2, u2, u3*u3)
            + fmaf(v0, v0, v1*v1) + fmaf(v2, v2, v3*v3);
    }
#pragma unroll
    for (int off = 16; off; off >>= 1) {
        s1 += __shfl_xor_sync(0xffffffffu, s1, off);
        s2 += __shfl_xor_sync(0xffffffffu, s2, off);
    }
    if ((tid & 31) == 0) {
        int w = tid >> 5;                 // warp w covers co [16w,16w+16) = GN group w
        int slot = (pb*NGROUPS + w)*NTILES + ptile;
        g_sum[slot] = s1;
        g_sq[slot]  = s2;
    }
}

// ---------------------------------------------------------------------------
// Kernel 0: Wq/Wk/Wv -> fp16 swizzled; Wo -> fp32 transposed (runs once)
// ---------------------------------------------------------------------------
extern "C" __global__ void prep_w(const float* __restrict__ wq, const float* __restrict__ wk,
                                  const float* __restrict__ wv, const float* __restrict__ wo) {
    int idx = blockIdx.x * 256 + threadIdx.x;   // 0..65535
    int m = idx >> 14, e = idx & 16383;
    int co = e >> 7, k = e & 127;
    if (m < 3) {
        const float* src = (m == 0) ? wq : (m == 1) ? wk : wv;
        g_w[m][swz(co, k) >> 1] = __float2half_rn(src[e]);
    } else {
        g_woT[k*CC + co] = wo[e];       // fp32 transpose, no rounding
    }
}

// ---------------------------------------------------------------------------
// staging helpers (256 threads)
// ---------------------------------------------------------------------------
__device__ __forceinline__ void copy32k(char* dst, const __half* __restrict__ src, int tid) {
    const float4* s = (const float4*)src;
    float4* d = (float4*)dst;
#pragma unroll
    for (int it = 0; it < 8; it++) d[it*256 + tid] = s[it*256 + tid];
}
__device__ __forceinline__ void copy64k(char* dst, const float* __restrict__ src, int tid) {
    const float4* s = (const float4*)src;
    float4* d = (float4*)dst;
#pragma unroll
    for (int it = 0; it < 16; it++) d[it*256 + tid] = s[it*256 + tid];
}

__device__ __forceinline__ void stage_load(uint32_t rh[16], const float* __restrict__ src, int tid) {
#pragma unroll
    for (int it = 0; it < 4; it++) {
        int c = it*256 + tid;
        int vox0 = (c & 15) * 4;
        int k0   = (c >> 4) * 2;
        float4 a = *(const float4*)(src + (size_t)k0*NVOX + vox0);
        float4 b = *(const float4*)(src + (size_t)(k0+1)*NVOX + vox0);
        rh[4*it+0] = pkhalf2(a.x, b.x);
        rh[4*it+1] = pkhalf2(a.y, b.y);
        rh[4*it+2] = pkhalf2(a.z, b.z);
        rh[4*it+3] = pkhalf2(a.w, b.w);
    }
}

__device__ __forceinline__ void stage_store(char* smb, uint32_t yoff, const uint32_t rh[16], int tid) {
#pragma unroll
    for (int it = 0; it < 4; it++) {
        int c = it*256 + tid;
        int vox0 = (c & 15) * 4;
        int k0   = (c >> 4) * 2;
#pragma unroll
        for (int v = 0; v < 4; v++)
            *(uint32_t*)(smb + yoff + swz(vox0 + v, k0)) = rh[4*it + v];
    }
}

// ---------------------------------------------------------------------------
// Kernel 1: persistent fused attention. Q/K/V on the tensor pipe; O-projection
// of the PREVIOUS unit runs on the FMA pipe interleaved with the cond loop.
// ---------------------------------------------------------------------------
extern "C" __global__ void __launch_bounds__(256, 1)
attn_fused(const float* __restrict__ skip, const float* __restrict__ dec,
           const float* __restrict__ bq, const float* __restrict__ bk,
           const float* __restrict__ bv, const float* __restrict__ bo,
           float* __restrict__ out)
{
    extern __shared__ char smraw[];
    char* smb = (char*)(((uintptr_t)smraw + 1023) & ~(uintptr_t)1023);
    const uint32_t sb = smem_to_u32(smb);

    const int tid = threadIdx.x;
    const int w = tid >> 5, lane = tid & 31;
    const int j4 = lane & 3;
    const int myNb = lane >> 2;
    const int co0 = (tid >> 4) * 8, n0 = (tid & 15) * 4;   // scalar-O mapping
    const uint32_t ybuf[2] = { sb + OFF_Y0, sb + OFF_Y1 };

    // one-time weight residency
    copy32k(smb + OFF_WQ, g_w[0], tid);
    copy32k(smb + OFF_WK, g_w[1], tid);
    copy32k(smb + OFF_WV, g_w[2], tid);
    copy64k(smb + OFF_WOT, g_woT, tid);

    int u = blockIdx.x;
    uint32_t rh[16];
    {
        uint32_t xr[16];
        stage_load(xr, dec + (size_t)(u >> 9)*CC*NVOX + (size_t)(u & 511)*TN, tid);
        stage_store(smb, OFF_Y0, xr, tid);
        stage_load(rh, skip + (size_t)(u >> 9)*NCOND*CC*NVOX + (size_t)(u & 511)*TN, tid);
    }
    __syncthreads();                     // weights + Y0 ready

    bool havePrev = false;
    int pb = 0, ptile = 0;

    for (; u < NUNITS; u += NCTA) {
        const int b = u >> 9, tile = u & 511;
        const size_t voxBase = (size_t)tile * TN;
        const float* skipb = skip + (size_t)b*NCOND*CC*NVOX + voxBase;

        // ---- Q projection from Y0 (tensor) ----
        float q[8][4];
#pragma unroll
        for (int nb = 0; nb < 8; nb++)
#pragma unroll
            for (int rr = 0; rr < 4; rr++) q[nb][rr] = 0.0f;
        gemm1(q, sb + OFF_WQ, ybuf[0], w, lane);
        add_bias_frag(q, bq, w, lane);

        float oacc[8][4];
#pragma unroll
        for (int nb = 0; nb < 8; nb++)
#pragma unroll
            for (int rr = 0; rr < 4; rr++) oacc[nb][rr] = 0.0f;

        // scalar-O accumulators for PREVIOUS unit
        ull of2[4][4];
#pragma unroll
        for (int p = 0; p < 4; p++)
#pragma unroll
            for (int jj = 0; jj < 4; jj++) of2[p][jj] = 0ull;

        float mA = -INFINITY, lA = 0.0f, mB = -INFINITY, lB = 0.0f;

        stage_store(smb, OFF_Y1, rh, tid);   // cond0 -> Y1
        __syncthreads();

        // cond cd lives in ybuf[(cd+1)&1]; staging writes ybuf[cd&1]
#pragma unroll
        for (int cd = 0; cd < NCOND; cd++) {
            const uint32_t ycur = ybuf[(cd+1) & 1];
            if (cd < 3) stage_load(rh, skipb + (size_t)(cd+1)*CC*NVOX, tid);

            float kf[8][4], vf[8][4];
#pragma unroll
            for (int nb = 0; nb < 8; nb++)
#pragma unroll
                for (int rr = 0; rr < 4; rr++) { kf[nb][rr] = 0.0f; vf[nb][rr] = 0.0f; }
            gemm1_kv(kf, vf, sb + OFF_WK, sb + OFF_WV, ycur, w, lane);

            if (cd < 3) stage_store(smb, (cd & 1) ? OFF_Y1 : OFF_Y0, rh, tid);

            // interleave scalar O (FMA pipe) for previous unit
            if (havePrev) {
                o_chunk(of2, smb, 2*cd,     co0, n0);
                o_chunk(of2, smb, 2*cd + 1, co0, n0);
            }

            add_bias_frag(kf, bk, w, lane);
            add_bias_frag(vf, bv, w, lane);

            // scores (head w lives entirely in warp w)
            float sOwnA = 0.0f, sOwnB = 0.0f;
#pragma unroll
            for (int nb = 0; nb < 8; nb++) {
                float pA = fmaf(q[nb][0], kf[nb][0], q[nb][2]*kf[nb][2]);
                float pB = fmaf(q[nb][1], kf[nb][1], q[nb][3]*kf[nb][3]);
#pragma unroll
                for (int off = 4; off <= 16; off <<= 1) {
                    pA += __shfl_xor_sync(0xffffffffu, pA, off);
                    pB += __shfl_xor_sync(0xffffffffu, pB, off);
                }
                if (myNb == nb) { sOwnA = pA; sOwnB = pB; }
            }

            sOwnA *= 0.25f;  sOwnB *= 0.25f;          // 1/sqrt(16)
            float mnA = fmaxf(mA, sOwnA);
            float corrA = __expf(mA - mnA);
            float pEA   = __expf(sOwnA - mnA);
            lA = lA*corrA + pEA;  mA = mnA;
            float mnB = fmaxf(mB, sOwnB);
            float corrB = __expf(mB - mnB);
            float pEB   = __expf(sOwnB - mnB);
            lB = lB*corrB + pEB;  mB = mnB;

#pragma unroll
            for (int nb = 0; nb < 8; nb++) {
                int srcl = nb*4 + j4;
                float c0 = __shfl_sync(0xffffffffu, corrA, srcl);
                float p0 = __shfl_sync(0xffffffffu, pEA,   srcl);
                float c1 = __shfl_sync(0xffffffffu, corrB, srcl);
                float p1 = __shfl_sync(0xffffffffu, pEB,   srcl);
                oacc[nb][0] = fmaf(oacc[nb][0], c0, p0*vf[nb][0]);
                oacc[nb][1] = fmaf(oacc[nb][1], c1, p1*vf[nb][1]);
                oacc[nb][2] = fmaf(oacc[nb][2], c0, p0*vf[nb][2]);
                oacc[nb][3] = fmaf(oacc[nb][3], c1, p1*vf[nb][3]);
            }

            if (cd < 3) __syncthreads();
        }

        // ---- previous unit's O epilogue (gmem only; Y2 reads all done) ----
        if (havePrev)
            o_epilogue(of2, dec, out, bo, pb, ptile, tid);

        __syncthreads();                 // all o_chunk Y2 reads done -> Y2 reusable

        // ---- finalize attention output of THIS unit -> Y2 (fp32 [co][vox]) ----
        {
            float* y2 = (float*)(smb + OFF_Y2);
            const int r0 = 16*w + (lane >> 2);
#pragma unroll
            for (int nb = 0; nb < 8; nb++) {
                int srcl = nb*4 + j4;
                float inv0 = 1.0f / __shfl_sync(0xffffffffu, lA, srcl);
                float inv1 = 1.0f / __shfl_sync(0xffffffffu, lB, srcl);
                int col = 8*nb + 2*j4;
                y2[ r0      *TN + col]     = oacc[nb][0]*inv0;
                y2[ r0      *TN + col + 1] = oacc[nb][1]*inv1;
                y2[(r0 + 8) *TN + col]     = oacc[nb][2]*inv0;
                y2[(r0 + 8) *TN + col + 1] = oacc[nb][3]*inv1;
            }
        }

        // ---- prefetch next unit's X and cond0 (overlaps Y2 writes) ----
        const bool more = (u + NCTA < NUNITS);
        if (more) {
            int un = u + NCTA;
            uint32_t xr[16];
            stage_load(xr, dec + (size_t)(un >> 9)*CC*NVOX + (size_t)(un & 511)*TN, tid);
            stage_store(smb, OFF_Y0, xr, tid);   // Y0 last read at cd3 (pre-barrier) — safe
            stage_load(rh, skip + (size_t)(un >> 9)*NCOND*CC*NVOX + (size_t)(un & 511)*TN, tid);
        }

        havePrev = true; pb = b; ptile = tile;
        __syncthreads();                 // Y2 + Y0(next) ready
    }

    // ---- drain: O projection + epilogue for this CTA's last unit ----
    if (havePrev) {
        ull of2[4][4];
#pragma unroll
        for (int p = 0; p < 4; p++)
#pragma unroll
            for (int jj = 0; jj < 4; jj++) of2[p][jj] = 0ull;
#pragma unroll
        for (int s = 0; s < 8; s++)
            o_chunk(of2, smb, s, co0, n0);
        o_epilogue(of2, dec, out, bo, pb, ptile, tid);
    }
}

// ---------------------------------------------------------------------------
// Kernel 2: reduce per-tile partials into per-(batch,group) mean / rstd
// ---------------------------------------------------------------------------
extern "C" __global__ void gn_stats() {
    __shared__ float sh1[256], sh2[256];
    const int bg = blockIdx.x;        // 0..15
    const int tid = threadIdx.x;
    const float* ps = g_sum + bg*NTILES;
    const float* pq = g_sq  + bg*NTILES;
    float s1 = ps[tid] + ps[tid+256];
    float s2 = pq[tid] + pq[tid+256];
    sh1[tid] = s1; sh2[tid] = s2;
    __syncthreads();
    for (int off = 128; off; off >>= 1) {
        if (tid < off) { sh1[tid] += sh1[tid+off]; sh2[tid] += sh2[tid+off]; }
        __syncthreads();
    }
    if (tid == 0) {
        const float cnt = (float)(16 * NVOX);      // 524288
        float mean = sh1[0] / cnt;
        float var  = sh2[0] / cnt - mean*mean;
        g_stats[bg] = make_float2(mean, rsqrtf(var + 1e-5f));
    }
}

// ---------------------------------------------------------------------------
// Kernel 3: apply GroupNorm affine in place
// ---------------------------------------------------------------------------
extern "C" __global__ void gn_apply(float* __restrict__ out,
                                    const float* __restrict__ gamma,
                                    const float* __restrict__ beta) {
    size_t elem = ((size_t)blockIdx.x * blockDim.x + threadIdx.x) * 4;
    int b = (int)(elem >> 22);
    int c = (int)((elem >> 15) & 127);
    float2 st = g_stats[b*NGROUPS + (c >> 4)];
    float ga = __ldg(&gamma[c]), be = __ldg(&beta[c]);
    float4 v = *(float4*)(out + elem);
    float sc = st.y * ga;
    v.x = (v.x - st.x)*sc + be;
    v.y = (v.y - st.x)*sc + be;
    v.z = (v.z - st.x)*sc + be;
    v.w = (v.w - st.x)*sc + be;
    *(float4*)(out + elem) = v;
}

// ---------------------------------------------------------------------------
extern "C" void kernel_launch(void* const* d_in, const int* in_sizes, int n_in,
                              void* d_out, int out_size) {
    const float* skip  = (const float*)d_in[0];
    const float* dec   = (const float*)d_in[1];
    const float* wq    = (const float*)d_in[2];
    const float* wk    = (const float*)d_in[3];
    const float* wv    = (const float*)d_in[4];
    const float* bq    = (const float*)d_in[5];
    const float* bk    = (const float*)d_in[6];
    const float* bv    = (const float*)d_in[7];
    const float* wo    = (const float*)d_in[8];
    const float* bo    = (const float*)d_in[9];
    const float* gamma = (const float*)d_in[10];
    const float* beta  = (const float*)d_in[11];
    float* out = (float*)d_out;

    cudaFuncSetAttribute(attn_fused, cudaFuncAttributeMaxDynamicSharedMemorySize, SMEM_REQ);

    prep_w<<<256, 256>>>(wq, wk, wv, wo);
    attn_fused<<<NCTA, 256, SMEM_REQ>>>(skip, dec, bq, bk, bv, bo, out);
    gn_stats<<<NB*NGROUPS, 256>>>();
    gn_apply<<<(NB*CC*NVOX/4)/256, 256>>>(out, gamma, beta);
}

// round 14
// speedup vs baseline: 1.4488x; 1.4488x over previous
#include <cuda_runtime.h>
#include <cuda_fp16.h>
#include <math.h>
#include <stdint.h>

// ---------------------------------------------------------------------------
// Problem constants
// ---------------------------------------------------------------------------
#define CC      128
#define TN      64
#define NCOND   4
#define NVOX    32768
#define NTILES  512
#define NB      2
#define NGROUPS 8
#define NUNITS  (NB*NTILES)     // 1024 (b, tile) work units
#define NCTA    148             // persistent CTAs (one per SM)

// smem byte offsets (from 1024-aligned base). One fp16 weight = 32KB.
#define OFF_WQ   0
#define OFF_WK   32768
#define OFF_WV   65536
#define OFF_WO   98304
#define OFF_Y0   131072     // activation buffer 0 [n=64][k=128] fp16 swizzled (16KB)
#define OFF_Y1   147456     // activation buffer 1 (16KB)
#define SMEM_REQ (163840 + 1024)

// ---------------------------------------------------------------------------
// global scratch (no allocations allowed)
// ---------------------------------------------------------------------------
__device__ float  g_sum[NB*NGROUPS*NTILES];
__device__ float  g_sq [NB*NGROUPS*NTILES];
__device__ float2 g_stats[NB*NGROUPS];
__device__ int    g_done = 0;       // self-resetting completion counter

// ---------------------------------------------------------------------------
// PTX wrappers (plain sm_80-era ISA)
// ---------------------------------------------------------------------------
__device__ __forceinline__ uint32_t smem_to_u32(const void* p) {
    uint32_t a;
    asm("{ .reg .u64 t; cvta.to.shared.u64 t, %1; cvt.u32.u64 %0, t; }" : "=r"(a) : "l"(p));
    return a;
}
__device__ __forceinline__ void ldsm4(uint32_t r[4], uint32_t addr) {
    asm volatile("ldmatrix.sync.aligned.m8n8.x4.shared.b16 {%0,%1,%2,%3}, [%4];"
                 : "=r"(r[0]), "=r"(r[1]), "=r"(r[2]), "=r"(r[3]) : "r"(addr));
}
__device__ __forceinline__ void mma16816(float d[4], const uint32_t a[4],
                                         uint32_t b0, uint32_t b1) {
    asm volatile("mma.sync.aligned.m16n8k16.row.col.f32.f16.f16.f32 "
                 "{%0,%1,%2,%3}, {%4,%5,%6,%7}, {%8,%9}, {%0,%1,%2,%3};"
                 : "+f"(d[0]), "+f"(d[1]), "+f"(d[2]), "+f"(d[3])
                 : "r"(a[0]), "r"(a[1]), "r"(a[2]), "r"(a[3]), "r"(b0), "r"(b1));
}

// swizzled byte offset inside a [rows][128] fp16 tile with 256B rows
__device__ __forceinline__ uint32_t swz(int row, int k) {
    return (uint32_t)(row * 256 + ((((k >> 3) ^ (row & 7)) & 15) << 4) + (k & 7) * 2);
}
__device__ __forceinline__ uint32_t pkhalf2(float lo, float hi) {
    __half2 h = __floats2half2_rn(lo, hi);
    uint32_t u;
    memcpy(&u, &h, 4);
    return u;
}

// ---------------------------------------------------------------------------
// fp16 MMA GEMMs (identical to the 160.2us kernel)
// ---------------------------------------------------------------------------
__device__ __forceinline__ void gemm1(float acc[8][4], uint32_t wa, uint32_t y,
                                      int w, int lane) {
    const int row  = lane & 15;
    const int half = lane >> 4;
#pragma unroll
    for (int kc = 0; kc < 8; kc++) {
        const uint32_t uoff = (uint32_t)((((2*kc + half) ^ (row & 7)) & 15) << 4);
        uint32_t A[4];
        ldsm4(A, wa + (uint32_t)(16*w + row)*256 + uoff);
#pragma unroll
        for (int nb2 = 0; nb2 < 4; nb2++) {
            uint32_t B[4];
            ldsm4(B, y + (uint32_t)(16*nb2 + row)*256 + uoff);
            mma16816(acc[2*nb2],   A, B[0], B[2]);
            mma16816(acc[2*nb2+1], A, B[1], B[3]);
        }
    }
}

__device__ __forceinline__ void gemm1_kv(float kf[8][4], float vf[8][4],
                                         uint32_t wk_, uint32_t wv_, uint32_t y,
                                         int w, int lane) {
    const int row  = lane & 15;
    const int half = lane >> 4;
#pragma unroll
    for (int kc = 0; kc < 8; kc++) {
        const uint32_t uoff = (uint32_t)((((2*kc + half) ^ (row & 7)) & 15) << 4);
        const uint32_t arow = (uint32_t)(16*w + row)*256 + uoff;
        uint32_t KA[4], VA[4];
        ldsm4(KA, wk_ + arow);
        ldsm4(VA, wv_ + arow);
#pragma unroll
        for (int nb2 = 0; nb2 < 4; nb2++) {
            uint32_t B[4];
            ldsm4(B, y + (uint32_t)(16*nb2 + row)*256 + uoff);
            mma16816(kf[2*nb2],   KA, B[0], B[2]);
            mma16816(kf[2*nb2+1], KA, B[1], B[3]);
            mma16816(vf[2*nb2],   VA, B[0], B[2]);
            mma16816(vf[2*nb2+1], VA, B[1], B[3]);
        }
    }
}

__device__ __forceinline__ void add_bias_frag(float acc[8][4], const float* __restrict__ bias,
                                              int w, int lane) {
    float b0 = __ldg(&bias[16*w + (lane >> 2)]);
    float b1 = __ldg(&bias[16*w + (lane >> 2) + 8]);
#pragma unroll
    for (int nb = 0; nb < 8; nb++) {
        acc[nb][0] += b0; acc[nb][1] += b0;
        acc[nb][2] += b1; acc[nb][3] += b1;
    }
}

// ---------------------------------------------------------------------------
// in-kernel weight conversion: fp32 global [co][k] -> fp16 swizzled smem.
// 4096 float4 / 256 thr = 16 float4/thread; each float4 covers 4 consecutive
// k at one co -> one aligned 8B STS inside a single swizzle unit.
// ---------------------------------------------------------------------------
__device__ __forceinline__ void conv_w(char* dst, const float* __restrict__ src, int tid) {
    const float4* s4 = (const float4*)src;
#pragma unroll
    for (int it = 0; it < 16; it++) {
        int i = it*256 + tid;          // float4 index 0..4095
        float4 v = s4[i];
        int e  = i * 4;                // element index
        int co = e >> 7;
        int k0 = e & 127;              // multiple of 4
        uint2 pk;
        pk.x = pkhalf2(v.x, v.y);
        pk.y = pkhalf2(v.z, v.w);
        uint32_t unit = (uint32_t)((((k0 >> 3) ^ (co & 7)) & 15));
        *(uint2*)(dst + co*256 + unit*16 + (k0 & 7)*2) = pk;
    }
}

// ---------------------------------------------------------------------------
// staging helpers (256 threads) — identical to the 160.2us kernel
// ---------------------------------------------------------------------------
__device__ __forceinline__ void stage_load(uint32_t rh[16], const float* __restrict__ src, int tid) {
#pragma unroll
    for (int it = 0; it < 4; it++) {
        int c = it*256 + tid;
        int vox0 = (c & 15) * 4;
        int k0   = (c >> 4) * 2;
        float4 a = *(const float4*)(src + (size_t)k0*NVOX + vox0);
        float4 b = *(const float4*)(src + (size_t)(k0+1)*NVOX + vox0);
        rh[4*it+0] = pkhalf2(a.x, b.x);
        rh[4*it+1] = pkhalf2(a.y, b.y);
        rh[4*it+2] = pkhalf2(a.z, b.z);
        rh[4*it+3] = pkhalf2(a.w, b.w);
    }
}

__device__ __forceinline__ void stage_store(char* smb, uint32_t yoff, const uint32_t rh[16], int tid) {
#pragma unroll
    for (int it = 0; it < 4; it++) {
        int c = it*256 + tid;
        int vox0 = (c & 15) * 4;
        int k0   = (c >> 4) * 2;
#pragma unroll
        for (int v = 0; v < 4; v++)
            *(uint32_t*)(smb + yoff + swz(vox0 + v, k0)) = rh[4*it + v];
    }
}

// ---------------------------------------------------------------------------
// Kernel 1: persistent fused attention (R12 structure, proven) +
// in-prologue weight conversion + last-CTA GN stats reduction.
// ---------------------------------------------------------------------------
extern "C" __global__ void __launch_bounds__(256, 1)
attn_fused(const float* __restrict__ skip, const float* __restrict__ dec,
           const float* __restrict__ wq, const float* __restrict__ wk,
           const float* __restrict__ wv, const float* __restrict__ wo,
           const float* __restrict__ bq, const float* __restrict__ bk,
           const float* __restrict__ bv, const float* __restrict__ bo,
           float* __restrict__ out)
{
    extern __shared__ char smraw[];
    char* smb = (char*)(((uintptr_t)smraw + 1023) & ~(uintptr_t)1023);
    const uint32_t sb = smem_to_u32(smb);

    const int tid = threadIdx.x;
    const int w = tid >> 5, lane = tid & 31;
    const int j4 = lane & 3;
    const int myNb = lane >> 2;
    const uint32_t ybuf[2] = { sb + OFF_Y0, sb + OFF_Y1 };

    // one-time weight conversion (fp32 global -> fp16 swizzled smem)
    conv_w(smb + OFF_WQ, wq, tid);
    conv_w(smb + OFF_WK, wk, tid);
    conv_w(smb + OFF_WV, wv, tid);
    conv_w(smb + OFF_WO, wo, tid);

    int u = blockIdx.x;
    uint32_t rh[16];
    {
        uint32_t xr[16];
        stage_load(xr, dec + (size_t)(u >> 9)*CC*NVOX + (size_t)(u & 511)*TN, tid);
        stage_store(smb, OFF_Y0, xr, tid);
        stage_load(rh, skip + (size_t)(u >> 9)*NCOND*CC*NVOX + (size_t)(u & 511)*TN, tid);
    }
    __syncthreads();                     // weights + Y0 ready

    for (; u < NUNITS; u += NCTA) {
        const int b = u >> 9, tile = u & 511;
        const size_t voxBase = (size_t)tile * TN;
        const float* decb  = dec  + (size_t)b*CC*NVOX + voxBase;
        const float* skipb = skip + (size_t)b*NCOND*CC*NVOX + voxBase;

        // ---- Q projection from Y0 ----
        float q[8][4];
#pragma unroll
        for (int nb = 0; nb < 8; nb++)
#pragma unroll
            for (int rr = 0; rr < 4; rr++) q[nb][rr] = 0.0f;
        gemm1(q, sb + OFF_WQ, ybuf[0], w, lane);
        add_bias_frag(q, bq, w, lane);

        float oacc[8][4];
#pragma unroll
        for (int nb = 0; nb < 8; nb++)
#pragma unroll
            for (int rr = 0; rr < 4; rr++) oacc[nb][rr] = 0.0f;

        float mA = -INFINITY, lA = 0.0f, mB = -INFINITY, lB = 0.0f;

        stage_store(smb, OFF_Y1, rh, tid);   // cond0 -> Y1
        __syncthreads();

        // cond cd lives in ybuf[(cd+1)&1]; staging writes ybuf[cd&1]
#pragma unroll
        for (int cd = 0; cd < NCOND; cd++) {
            const uint32_t ycur = ybuf[(cd+1) & 1];
            if (cd < 3) stage_load(rh, skipb + (size_t)(cd+1)*CC*NVOX, tid);

            float kf[8][4], vf[8][4];
#pragma unroll
            for (int nb = 0; nb < 8; nb++)
#pragma unroll
                for (int rr = 0; rr < 4; rr++) { kf[nb][rr] = 0.0f; vf[nb][rr] = 0.0f; }
            gemm1_kv(kf, vf, sb + OFF_WK, sb + OFF_WV, ycur, w, lane);

            if (cd < 3) stage_store(smb, (cd & 1) ? OFF_Y1 : OFF_Y0, rh, tid);

            add_bias_frag(kf, bk, w, lane);
            add_bias_frag(vf, bv, w, lane);

            // scores (head w lives entirely in warp w)
            float sOwnA = 0.0f, sOwnB = 0.0f;
#pragma unroll
            for (int nb = 0; nb < 8; nb++) {
                float pA = fmaf(q[nb][0], kf[nb][0], q[nb][2]*kf[nb][2]);
                float pB = fmaf(q[nb][1], kf[nb][1], q[nb][3]*kf[nb][3]);
#pragma unroll
                for (int off = 4; off <= 16; off <<= 1) {
                    pA += __shfl_xor_sync(0xffffffffu, pA, off);
                    pB += __shfl_xor_sync(0xffffffffu, pB, off);
                }
                if (myNb == nb) { sOwnA = pA; sOwnB = pB; }
            }

            sOwnA *= 0.25f;  sOwnB *= 0.25f;          // 1/sqrt(head_dim=16)
            float mnA = fmaxf(mA, sOwnA);
            float corrA = __expf(mA - mnA);
            float pEA   = __expf(sOwnA - mnA);
            lA = lA*corrA + pEA;  mA = mnA;
            float mnB = fmaxf(mB, sOwnB);
            float corrB = __expf(mB - mnB);
            float pEB   = __expf(sOwnB - mnB);
            lB = lB*corrB + pEB;  mB = mnB;

#pragma unroll
            for (int nb = 0; nb < 8; nb++) {
                int srcl = nb*4 + j4;
                float c0 = __shfl_sync(0xffffffffu, corrA, srcl);
                float p0 = __shfl_sync(0xffffffffu, pEA,   srcl);
                float c1 = __shfl_sync(0xffffffffu, corrB, srcl);
                float p1 = __shfl_sync(0xffffffffu, pEB,   srcl);
                oacc[nb][0] = fmaf(oacc[nb][0], c0, p0*vf[nb][0]);
                oacc[nb][1] = fmaf(oacc[nb][1], c1, p1*vf[nb][1]);
                oacc[nb][2] = fmaf(oacc[nb][2], c0, p0*vf[nb][2]);
                oacc[nb][3] = fmaf(oacc[nb][3], c1, p1*vf[nb][3]);
            }

            if (cd < 3) __syncthreads();
        }

        // ---- attention output -> Y1 (fp16) ----
        {
            const int r0 = 16*w + (lane >> 2);
#pragma unroll
            for (int nb = 0; nb < 8; nb++) {
                int srcl = nb*4 + j4;
                float inv0 = 1.0f / __shfl_sync(0xffffffffu, lA, srcl);
                float inv1 = 1.0f / __shfl_sync(0xffffffffu, lB, srcl);
                int col = 8*nb + 2*j4;
                *(__half*)(smb + OFF_Y1 + swz(col,     r0    )) = __float2half_rn(oacc[nb][0]*inv0);
                *(__half*)(smb + OFF_Y1 + swz(col + 1, r0    )) = __float2half_rn(oacc[nb][1]*inv1);
                *(__half*)(smb + OFF_Y1 + swz(col,     r0 + 8)) = __float2half_rn(oacc[nb][2]*inv0);
                *(__half*)(smb + OFF_Y1 + swz(col + 1, r0 + 8)) = __float2half_rn(oacc[nb][3]*inv1);
            }
        }
        __syncthreads();                 // attention writes visible; Y0 free

        // ---- next unit X staging overlaps O projection ----
        const bool more = (u + NCTA < NUNITS);
        uint32_t xr[16];
        if (more) {
            int un = u + NCTA;
            stage_load(xr, dec + (size_t)(un >> 9)*CC*NVOX + (size_t)(un & 511)*TN, tid);
        }

        float of[8][4];
#pragma unroll
        for (int nb = 0; nb < 8; nb++)
#pragma unroll
            for (int rr = 0; rr < 4; rr++) of[nb][rr] = 0.0f;
        gemm1(of, sb + OFF_WO, ybuf[1], w, lane);

        if (more) stage_store(smb, OFF_Y0, xr, tid);

        // ---- fragment-direct epilogue: bias + residual + store + GN ----
        {
            const int r0 = 16*w + (lane >> 2);
            const float bo0 = __ldg(&bo[r0]);
            const float bo1 = __ldg(&bo[r0 + 8]);
            float* outb = out + (size_t)b*CC*NVOX + voxBase;
            float s1 = 0.0f, s2 = 0.0f;
#pragma unroll
            for (int nb = 0; nb < 8; nb++) {
                int col = 8*nb + 2*j4;
                float2 rv0 = *(const float2*)(decb + (size_t)r0*NVOX + col);
                float2 rv1 = *(const float2*)(decb + (size_t)(r0+8)*NVOX + col);
                float u0 = of[nb][0] + bo0 + rv0.x;
                float u1 = of[nb][1] + bo0 + rv0.y;
                float u2 = of[nb][2] + bo1 + rv1.x;
                float u3 = of[nb][3] + bo1 + rv1.y;
                *(float2*)(outb + (size_t)r0*NVOX + col)     = make_float2(u0, u1);
                *(float2*)(outb + (size_t)(r0+8)*NVOX + col) = make_float2(u2, u3);
                s1 += (u0 + u1) + (u2 + u3);
                s2 += fmaf(u0, u0, u1*u1) + fmaf(u2, u2, u3*u3);
            }
#pragma unroll
            for (int off = 16; off; off >>= 1) {
                s1 += __shfl_xor_sync(0xffffffffu, s1, off);
                s2 += __shfl_xor_sync(0xffffffffu, s2, off);
            }
            if (lane == 0) {
                int slot = (b*NGROUPS + w)*NTILES + tile;   // warp w == GN group w
                g_sum[slot] = s1;
                g_sq[slot]  = s2;
            }
        }

        if (more) {
            int un = u + NCTA;
            stage_load(rh, skip + (size_t)(un >> 9)*NCOND*CC*NVOX + (size_t)(un & 511)*TN, tid);
        }
        __syncthreads();                 // Y0(next) ready; O gemm reads done
    }

    // ---- last CTA reduces GN partials into g_stats (replaces gn_stats) ----
    __shared__ int sIsLast;
    if (tid == 0) {
        __threadfence();
        int old = atomicAdd(&g_done, 1);
        sIsLast = (old == NCTA - 1) ? 1 : 0;
    }
    __syncthreads();
    if (sIsLast) {
        __threadfence();                 // acquire all CTAs' g_sum/g_sq writes
        // 16 (b,group) rows of 512 partials; 16 threads per row, each sums 32
        int bg = tid >> 4;               // 0..15
        int sl = tid & 15;
        const float* ps = g_sum + bg*NTILES;
        const float* pq = g_sq  + bg*NTILES;
        float s1 = 0.0f, s2 = 0.0f;
#pragma unroll
        for (int k = 0; k < 32; k++) { s1 += ps[sl + 16*k]; s2 += pq[sl + 16*k]; }
#pragma unroll
        for (int off = 8; off; off >>= 1) {
            s1 += __shfl_xor_sync(0xffffffffu, s1, off);
            s2 += __shfl_xor_sync(0xffffffffu, s2, off);
        }
        if (sl == 0) {
            const float cnt = (float)(16 * NVOX);    // 524288
            float mean = s1 / cnt;
            float var  = s2 / cnt - mean*mean;
            g_stats[bg] = make_float2(mean, rsqrtf(var + 1e-5f));
        }
        if (tid == 0) g_done = 0;        // self-reset for next graph replay
    }
}

// ---------------------------------------------------------------------------
// Kernel 2: apply GroupNorm affine in place
// ---------------------------------------------------------------------------
extern "C" __global__ void gn_apply(float* __restrict__ out,
                                    const float* __restrict__ gamma,
                                    const float* __restrict__ beta) {
    size_t elem = ((size_t)blockIdx.x * blockDim.x + threadIdx.x) * 4;
    int b = (int)(elem >> 22);
    int c = (int)((elem >> 15) & 127);
    float2 st = g_stats[b*NGROUPS + (c >> 4)];
    float ga = __ldg(&gamma[c]), be = __ldg(&beta[c]);
    float4 v = *(float4*)(out + elem);
    float sc = st.y * ga;
    v.x = (v.x - st.x)*sc + be;
    v.y = (v.y - st.x)*sc + be;
    v.z = (v.z - st.x)*sc + be;
    v.w = (v.w - st.x)*sc + be;
    __stcs((float4*)(out + elem), v);
}

// ---------------------------------------------------------------------------
extern "C" void kernel_launch(void* const* d_in, const int* in_sizes, int n_in,
                              void* d_out, int out_size) {
    const float* skip  = (const float*)d_in[0];
    const float* dec   = (const float*)d_in[1];
    const float* wq    = (const float*)d_in[2];
    const float* wk    = (const float*)d_in[3];
    const float* wv    = (const float*)d_in[4];
    const float* bq    = (const float*)d_in[5];
    const float* bk    = (const float*)d_in[6];
    const float* bv    = (const float*)d_in[7];
    const float* wo    = (const float*)d_in[8];
    const float* bo    = (const float*)d_in[9];
    const float* gamma = (const float*)d_in[10];
    const float* beta  = (const float*)d_in[11];
    float* out = (float*)d_out;

    cudaFuncSetAttribute(attn_fused, cudaFuncAttributeMaxDynamicSharedMemorySize, SMEM_REQ);

    attn_fused<<<NCTA, 256, SMEM_REQ>>>(skip, dec, wq, wk, wv, wo,
                                        bq, bk, bv, bo, out);
    gn_apply<<<(NB*CC*NVOX/4)/256, 256>>>(out, gamma, beta);
}